// round 4
// baseline (speedup 1.0000x reference)
#include <cuda_runtime.h>
#include <cuda_bf16.h>

// RGBToHVI: elementwise per-pixel transform, planar (N=16, C=3, H*W=1024*1024) fp32.
// HBM-bound: 24 B/pixel, ~402 MB total. float4 vectorization, fast MUFU intrinsics.

#define PLANE4   262144            // (1024*1024)/4 float4 per channel plane
#define NPIX4    4194304           // 16 * PLANE4
#define EPS_F    1e-8f
#define PI_F     3.14159265358979f

__global__ __launch_bounds__(256, 8)
void rgb_to_hvi_kernel(const float4* __restrict__ img,
                       const float*  __restrict__ dk,
                       float4* __restrict__ out)
{
    const int i = blockIdx.x * blockDim.x + threadIdx.x;
    if (i >= NPIX4) return;

    const float k = __ldg(dk);

    const int batch = i >> 18;              // / PLANE4
    const int w     = i & (PLANE4 - 1);
    const long base = (long)batch * (3 * PLANE4) + w;

    // Three front-batched 128-bit loads (MLP for latency hiding)
    const float4 rv = img[base];
    const float4 gv = img[base + PLANE4];
    const float4 bv = img[base + 2 * PLANE4];

    float4 Xv, Yv, Zv;
    const float* rp = (const float*)&rv;
    const float* gp = (const float*)&gv;
    const float* bp = (const float*)&bv;
    float* Xp = (float*)&Xv;
    float* Yp = (float*)&Yv;
    float* Zp = (float*)&Zv;

#pragma unroll
    for (int j = 0; j < 4; ++j) {
        const float r = rp[j];
        const float g = gp[j];
        const float b = bp[j];

        const float v  = fmaxf(r, fmaxf(g, b));
        const float mn = fminf(r, fminf(g, b));
        const float chroma = v - mn;
        const float rd = __frcp_rn(chroma + EPS_F);   // 1 / denom

        // jnp.where cascade: later where wins -> priority (highest first):
        //   mn == v  -> 0
        //   r  == v  -> ((g-b)/denom) mod 6
        //   g  == v  -> 2 + (b-r)/denom
        //   b  == v  -> 4 + (r-g)/denom
        //   else     -> 0
        float hue;
        if (mn == v) {
            hue = 0.0f;
        } else if (r == v) {
            float h = (g - b) * rd;                  // in [-1, 1]
            hue = (h < 0.0f) ? h + 6.0f : h;          // x % 6.0 with divisor-sign semantics
        } else if (g == v) {
            hue = 2.0f + (b - r) * rd;
        } else if (b == v) {
            hue = 4.0f + (r - g) * rd;
        } else {
            hue = 0.0f;
        }
        hue *= (1.0f / 6.0f);

        const float sat = (v == 0.0f) ? 0.0f : chroma * __frcp_rn(v + EPS_F);

        // color_sensitive = (sin(v * pi/2) + eps)^k   (v in [0,1] -> sin >= 0)
        const float s  = __sinf(v * (0.5f * PI_F)) + EPS_F;
        const float cs = __powf(s, k);

        const float ang = (2.0f * PI_F) * hue;        // [0, 2*pi)
        const float cx = __cosf(ang);
        const float cy = __sinf(ang);

        const float m = cs * sat;
        Xp[j] = m * cx;
        Yp[j] = m * cy;
        Zp[j] = v;
    }

    out[base]               = Xv;
    out[base + PLANE4]      = Yv;
    out[base + 2 * PLANE4]  = Zv;
}

extern "C" void kernel_launch(void* const* d_in, const int* in_sizes, int n_in,
                              void* d_out, int out_size)
{
    const float4* img = (const float4*)d_in[0];
    const float*  dk  = (const float*)d_in[1];
    float4* out = (float4*)d_out;

    const int threads = 256;
    const int blocks  = (NPIX4 + threads - 1) / threads;   // 16384
    rgb_to_hvi_kernel<<<blocks, threads>>>(img, dk, out);
}